// round 10
// baseline (speedup 1.0000x reference)
#include <cuda_runtime.h>
#include <stdint.h>

// B=8, T=8, C=1024, F=4, N=8192
#define TT 8
#define BB 8
#define CC 1024
#define FF 4
#define NN (TT*CC)
#define TB 64                   // (t,b) pairs
#define SW 4                    // strip width (columns staged in smem)
#define JQ 16                   // column units per (t,b)
#define UNITS (TB*JQ)           // 1024 CTAs, all resident at 7/SM
#define STRIPS 16               // 64 cols per unit / SW
#define NTHREADS 256
#define KITER 16                // 1024 rows / 64 row-groups
#define ROWS_PT 4               // rows per thread in phase 2
#define NSTRIDE 1032            // 1032%32==8 -> STS banks 8c+r all distinct
#define SMEM_BYTES ((SW*NSTRIDE + SW*FF + SW)*4)   // ~16.6 KB -> 7 CTAs/SM

// per-unit partial results [unit][i][f] : 16 MB scratch
__device__ float g_partial[(size_t)UNITS * CC * FF];

__device__ __forceinline__ uint32_t tf_rotl(uint32_t x, int d) {
    return __funnelshift_l(x, x, d);
}

// JAX threefry2x32 partitionable: key=(0,42), counter=(0,e), out = x0^x1.
// Takes y = e + 42 (key pre-injected). Round 1 simplified (x0 starts 0);
// key-schedule x0-injections fused into the next round-add (IADD3).
__device__ __forceinline__ uint32_t threefry_bits(uint32_t y) {
    const uint32_t K1 = 42u;
    const uint32_t K2 = 0x1BD11BDAu ^ 42u;
    uint32_t x0 = y;
    uint32_t x1 = tf_rotl(y, 13) ^ y;
#define TF_R(d) { x0 += x1; x1 = tf_rotl(x1,(d)) ^ x0; }
    TF_R(15) TF_R(26) TF_R(6)
    x1 += K2 + 1u;
    x0 += x1 + K1;
    x1 = tf_rotl(x1, 17) ^ x0;
    TF_R(29) TF_R(16) TF_R(24)
    x1 += 2u;
    x0 += x1 + K2;
    x1 = tf_rotl(x1, 13) ^ x0;
    TF_R(15) TF_R(26) TF_R(6)
    x1 += K1 + 3u;
    x0 += x1;
    x1 = tf_rotl(x1, 17) ^ x0;
    TF_R(29) TF_R(16) TF_R(24)
    x1 += K2 + 4u;
    x0 += x1 + K1;
    x1 = tf_rotl(x1, 13) ^ x0;
    TF_R(15) TF_R(26) TF_R(6)
    return (x0 + K2) ^ (x1 + 5u);
#undef TF_R
}

__device__ __forceinline__ float ex2_fast(float a) {
    float r;
    asm("ex2.approx.ftz.f32 %0, %1;" : "=f"(r) : "f"(a));
    return r;
}
__device__ __forceinline__ unsigned long long pack2(float v) {
    unsigned long long d;
    const uint32_t r = __float_as_uint(v);
    asm("mov.b64 %0, {%1, %1};" : "=l"(d) : "r"(r));
    return d;
}
__device__ __forceinline__ void ffma2(unsigned long long& acc,
                                      unsigned long long a,
                                      unsigned long long b) {
    asm("fma.rn.f32x2 %0, %1, %2, %0;" : "+l"(acc) : "l"(a), "l"(b));
}

// One unit = (tb, jq): 64 columns x 1024 rows of one (t,b) weight matrix.
// Per strip: num = exp(w + g) up to the softmax-invariant scale, computed as
// ex2(w*log2e - log2(-ln u)). -ln u: exact v=1-u (Sterbenz) + 3-term series
// for u->1 (relative accuracy where it matters), MUFU lg2 elsewhere.
__global__ __launch_bounds__(NTHREADS, 7)
void fused_retina_kernel(const float* __restrict__ x,
                         const float* __restrict__ w) {
    const int unit = blockIdx.x;
    const int tb = unit >> 4;
    const int jq = unit & (JQ - 1);
    const int t  = tb >> 3;
    const int b  = tb & 7;
    const int jbase = jq * (STRIPS * SW);

    extern __shared__ float smem[];
    float* num  = smem;                     // [SW][NSTRIDE]
    float* sxs  = num + SW * NSTRIDE;       // [SW][FF], 16B aligned
    float* csum = sxs + SW * FF;            // [SW]

    const int tid = threadIdx.x;
    const int c   = tid & (SW - 1);         // column within strip
    const int r   = tid >> 2;               // 0..63 row group

    unsigned long long acc[ROWS_PT][2] = {};  // packed f32x2 accumulators
    const uint32_t ebase = ((uint32_t)tb << 20);

    for (int s = 0; s < STRIPS; ++s) {
        const int j0 = jbase + s * SW;
        if (tid < SW) csum[tid] = 0.f;
        __syncthreads();

        // ---- phase 1: hash + numerator + column partial sums ----
        const int j = j0 + c;
        const float* wcol = w + ((size_t)tb << 20) + ((size_t)r << 10) + j;
        // counter with key pre-injected: y = e + 42
        const uint32_t y0 = (ebase | ((uint32_t)r << 10) | (uint32_t)j) + 42u;
        float part = 0.f;
        #pragma unroll 4
        for (int k = 0; k < KITER; ++k) {
            const int i = (k << 6) + r;
            const float ww = __ldg(wcol + ((size_t)k << 16));
            const uint32_t bits = threefry_bits(y0 + ((uint32_t)k << 16));
            // (bits>>9)|0x3f800000 as IMAD.HI + IADD (exact, disjoint bits)
            const uint32_t ub = __umulhi(bits, 1u << 23) + 0x3f800000u;
            const float f = __uint_as_float(ub) - 1.0f;
            const float u = fmaxf(f, 1.17549435e-38f);
            // -ln u: exact series near u=1, else lg2(u) * -ln2
            const float v = 1.0f - u;
            const float poly = fmaf(v * v, fmaf(v, 0.33333333f, 0.5f), v);
            const float l2u = __log2f(u);
            const float p = (v <= 0.015625f) ? poly : (l2u * -0.69314718f);
            // nv = 2^(w*log2e - log2(p)) = exp(w)/(-ln u)
            const float nv = ex2_fast(fmaf(ww, 1.44269504f, -__log2f(p)));
            num[c * NSTRIDE + i] = nv;
            part += nv;
        }
        // warp covers 8 row-groups x 4 cols: fold rows, 4 atomics per warp
        part += __shfl_xor_sync(0xffffffffu, part, 4);
        part += __shfl_xor_sync(0xffffffffu, part, 8);
        part += __shfl_xor_sync(0xffffffffu, part, 16);
        if ((tid & 31) < SW) atomicAdd(&csum[c], part);
        __syncthreads();

        // ---- scaled gather: sxs[jj][f] = x[b, jg*8+t, f] / colsum[jj] ----
        if (tid < SW * FF) {
            const int cc2 = tid >> 2, ff = tid & 3;
            const int jg = j0 + cc2;
            const float gx = x[((size_t)b * NN + jg * TT + t) * FF + ff];
            sxs[tid] = gx / csum[cc2];
        }
        __syncthreads();

        // ---- phase 2: acc[m][f] += sum_jj num[i, jj] * sxs[jj][f] ----
        #pragma unroll
        for (int jj = 0; jj < SW; ++jj) {
            const ulonglong2 s2 =
                *reinterpret_cast<const ulonglong2*>(&sxs[jj * FF]);
            #pragma unroll
            for (int m = 0; m < ROWS_PT; ++m) {
                const unsigned long long nvp =
                    pack2(num[jj * NSTRIDE + tid + m * NTHREADS]);
                ffma2(acc[m][0], nvp, s2.x);
                ffma2(acc[m][1], nvp, s2.y);
            }
        }
        __syncthreads();
    }

    ulonglong2* p = reinterpret_cast<ulonglong2*>(g_partial) +
                    ((size_t)unit * CC + tid);
    #pragma unroll
    for (int m = 0; m < ROWS_PT; ++m)
        p[m * NTHREADS] = make_ulonglong2(acc[m][0], acc[m][1]);
}

// Reduce: 2 threads per output (8 partials each), shfl combine, scatter.
__global__ void reduce_scatter_kernel(float* __restrict__ out) {
    const int gid = blockIdx.x * blockDim.x + threadIdx.x;  // [0, TB*CC*2)
    const int o  = gid >> 1;
    const int h  = gid & 1;
    const int i  = o & (CC - 1);
    const int tb = o >> 10;
    const int t = tb >> 3, b = tb & 7;
    const float4* pp = reinterpret_cast<const float4*>(g_partial);
    float4 a = make_float4(0.f, 0.f, 0.f, 0.f);
    #pragma unroll
    for (int q = 0; q < 8; ++q) {
        const float4 p = pp[(size_t)(tb * JQ + h * 8 + q) * CC + i];
        a.x += p.x; a.y += p.y; a.z += p.z; a.w += p.w;
    }
    a.x += __shfl_xor_sync(0xffffffffu, a.x, 1);
    a.y += __shfl_xor_sync(0xffffffffu, a.y, 1);
    a.z += __shfl_xor_sync(0xffffffffu, a.z, 1);
    a.w += __shfl_xor_sync(0xffffffffu, a.w, 1);
    if (h == 0)
        reinterpret_cast<float4*>(out)[(size_t)b * NN + i * TT + t] = a;
}

extern "C" void kernel_launch(void* const* d_in, const int* in_sizes, int n_in,
                              void* d_out, int out_size) {
    const float* x = (const float*)d_in[0];
    const float* w = (const float*)d_in[1];
    float* out = (float*)d_out;
    (void)in_sizes; (void)n_in; (void)out_size;

    cudaFuncSetAttribute(fused_retina_kernel,
                         cudaFuncAttributeMaxDynamicSharedMemorySize, SMEM_BYTES);
    fused_retina_kernel<<<UNITS, NTHREADS, SMEM_BYTES>>>(x, w);
    reduce_scatter_kernel<<<(TB * CC * 2) / 256, 256>>>(out);
}

// round 11
// speedup vs baseline: 1.4862x; 1.4862x over previous
#include <cuda_runtime.h>
#include <stdint.h>

// B=8, T=8, C=1024, F=4, N=8192
#define TT 8
#define BB 8
#define CC 1024
#define FF 4
#define NN (TT*CC)
#define TB 64                   // (t,b) pairs
#define SW 16                   // strip width (columns staged in smem)
#define JQ 32                   // column units per (t,b)  (fine-grained balance)
#define UNITS (TB*JQ)           // 2048 CTAs -> 6.92 per slot, tail ~1%
#define STRIPS 2                // 32 cols per unit / SW
#define NTHREADS 1024
#define KITER 16                // 1024 rows / 64 row-groups
#define NSTRIDE 1026            // EVEN stride: half-warps hit opposite bank parity
#define SMEM_BYTES ((SW*NSTRIDE + SW*FF + SW)*4)   // 65984 B -> 2 CTAs/SM

// per-unit partial results [unit][i][f] : 33.5 MB scratch
__device__ float g_partial[(size_t)UNITS * CC * FF];

__device__ __forceinline__ uint32_t tf_rotl(uint32_t x, int d) {
    return __funnelshift_l(x, x, d);
}

// JAX threefry2x32 partitionable: key=(0,42), counter=(0,e), out = x0^x1.
// Takes y = e + 42 (key pre-injected). Round 1 simplified (x0 starts 0);
// key-schedule x0-injections fused into the next round-add (IADD3).
__device__ __forceinline__ uint32_t threefry_bits(uint32_t y) {
    const uint32_t K1 = 42u;
    const uint32_t K2 = 0x1BD11BDAu ^ 42u;
    uint32_t x0 = y;
    uint32_t x1 = tf_rotl(y, 13) ^ y;
#define TF_R(d) { x0 += x1; x1 = tf_rotl(x1,(d)) ^ x0; }
    TF_R(15) TF_R(26) TF_R(6)
    x1 += K2 + 1u;
    x0 += x1 + K1;
    x1 = tf_rotl(x1, 17) ^ x0;
    TF_R(29) TF_R(16) TF_R(24)
    x1 += 2u;
    x0 += x1 + K2;
    x1 = tf_rotl(x1, 13) ^ x0;
    TF_R(15) TF_R(26) TF_R(6)
    x1 += K1 + 3u;
    x0 += x1;
    x1 = tf_rotl(x1, 17) ^ x0;
    TF_R(29) TF_R(16) TF_R(24)
    x1 += K2 + 4u;
    x0 += x1 + K1;
    x1 = tf_rotl(x1, 13) ^ x0;
    TF_R(15) TF_R(26) TF_R(6)
    return (x0 + K2) ^ (x1 + 5u);
#undef TF_R
}

__device__ __forceinline__ float ex2_fast(float a) {
    float r;
    asm("ex2.approx.ftz.f32 %0, %1;" : "=f"(r) : "f"(a));
    return r;
}
__device__ __forceinline__ unsigned long long pack2(float v) {
    unsigned long long d;
    const uint32_t r = __float_as_uint(v);
    asm("mov.b64 %0, {%1, %1};" : "=l"(d) : "r"(r));
    return d;
}
__device__ __forceinline__ void ffma2(unsigned long long& acc,
                                      unsigned long long a,
                                      unsigned long long b) {
    asm("fma.rn.f32x2 %0, %1, %2, %0;" : "+l"(acc) : "l"(a), "l"(b));
}

// One unit = (tb, jq): 32 columns x 1024 rows of one (t,b) weight matrix.
// Per strip: num = exp(w + g) up to the softmax-invariant scale, computed as
// ex2(w*log2e - log2(-ln u)). -ln u: exact v=1-u (Sterbenz) + 3-term series
// for u->1 (relative accuracy where it matters), MUFU lg2 elsewhere.
__global__ __launch_bounds__(NTHREADS, 2)
void fused_retina_kernel(const float* __restrict__ x,
                         const float* __restrict__ w) {
    const int unit = blockIdx.x;
    const int tb = unit >> 5;               // / JQ
    const int jq = unit & (JQ - 1);
    const int t  = tb >> 3;
    const int b  = tb & 7;
    const int jbase = jq * (STRIPS * SW);   // 32 cols per unit

    extern __shared__ float smem[];
    float* num  = smem;                     // [SW][NSTRIDE]
    float* sxs  = num + SW * NSTRIDE;       // [SW][FF], 16B aligned
    float* csum = sxs + SW * FF;            // [SW]

    const int tid = threadIdx.x;
    const int c   = tid & (SW - 1);         // column within strip
    const int r   = tid >> 4;               // 0..63 row group

    unsigned long long acc01 = 0ull, acc23 = 0ull;  // packed f32x2 accum
    const uint32_t ebase = ((uint32_t)tb << 20);

    for (int s = 0; s < STRIPS; ++s) {
        const int j0 = jbase + s * SW;
        if (tid < SW) csum[tid] = 0.f;
        __syncthreads();

        // ---- phase 1: hash + numerator + column partial sums ----
        const int j = j0 + c;
        const float* wcol = w + ((size_t)tb << 20) + ((size_t)r << 10) + j;
        // counter with key pre-injected: y = e + 42
        const uint32_t y0 = (ebase | ((uint32_t)r << 10) | (uint32_t)j) + 42u;
        float part = 0.f;
        #pragma unroll 4
        for (int k = 0; k < KITER; ++k) {
            const int i = (k << 6) + r;
            const float ww = __ldg(wcol + ((size_t)k << 16));
            const uint32_t bits = threefry_bits(y0 + ((uint32_t)k << 16));
            // (bits>>9)|0x3f800000 as IMAD.HI + IADD (exact, disjoint bits)
            const uint32_t ub = __umulhi(bits, 1u << 23) + 0x3f800000u;
            const float f = __uint_as_float(ub) - 1.0f;
            const float u = fmaxf(f, 1.17549435e-38f);
            // -ln u: exact series near u=1, else lg2(u) * -ln2
            const float v = 1.0f - u;
            const float poly = fmaf(v * v, fmaf(v, 0.33333333f, 0.5f), v);
            const float l2u = __log2f(u);
            const float p = (v <= 0.015625f) ? poly : (l2u * -0.69314718f);
            // nv = 2^(w*log2e - log2(p)) = exp(w)/(-ln u)
            const float nv = ex2_fast(fmaf(ww, 1.44269504f, -__log2f(p)));
            num[c * NSTRIDE + i] = nv;
            part += nv;
        }
        // lanes l and l^16 share a column: pre-reduce, then 16 atomics/warp
        part += __shfl_xor_sync(0xffffffffu, part, 16);
        if ((tid & 31) < SW) atomicAdd(&csum[c], part);
        __syncthreads();

        // ---- scaled gather: sxs[jj][f] = x[b, jg*8+t, f] / colsum[jj] ----
        if (tid < SW * FF) {
            const int cc2 = tid >> 2, ff = tid & 3;
            const int jg = j0 + cc2;
            const float gx = x[((size_t)b * NN + jg * TT + t) * FF + ff];
            sxs[tid] = gx / csum[cc2];
        }
        __syncthreads();

        // ---- phase 2: acc[f] += sum_jj num[tid, jj] * sxs[jj][f] ----
        #pragma unroll
        for (int jj = 0; jj < SW; ++jj) {
            const ulonglong2 s2 =
                *reinterpret_cast<const ulonglong2*>(&sxs[jj * FF]);
            const unsigned long long nvp = pack2(num[jj * NSTRIDE + tid]);
            ffma2(acc01, nvp, s2.x);
            ffma2(acc23, nvp, s2.y);
        }
        __syncthreads();
    }

    ulonglong2* p = reinterpret_cast<ulonglong2*>(g_partial) +
                    ((size_t)unit * CC + tid);
    *p = make_ulonglong2(acc01, acc23);
}

// Reduce: 4 threads per output (8 partials each), shfl combine, scatter.
__global__ void reduce_scatter_kernel(float* __restrict__ out) {
    const int gid = blockIdx.x * blockDim.x + threadIdx.x;  // [0, TB*CC*4)
    const int o  = gid >> 2;
    const int h  = gid & 3;
    const int i  = o & (CC - 1);
    const int tb = o >> 10;
    const int t = tb >> 3, b = tb & 7;
    const float4* pp = reinterpret_cast<const float4*>(g_partial);
    float4 a = make_float4(0.f, 0.f, 0.f, 0.f);
    #pragma unroll
    for (int q = 0; q < 8; ++q) {
        const float4 p = pp[(size_t)(tb * JQ + h * 8 + q) * CC + i];
        a.x += p.x; a.y += p.y; a.z += p.z; a.w += p.w;
    }
    #pragma unroll
    for (int m = 1; m < 4; m <<= 1) {
        a.x += __shfl_xor_sync(0xffffffffu, a.x, m);
        a.y += __shfl_xor_sync(0xffffffffu, a.y, m);
        a.z += __shfl_xor_sync(0xffffffffu, a.z, m);
        a.w += __shfl_xor_sync(0xffffffffu, a.w, m);
    }
    if (h == 0)
        reinterpret_cast<float4*>(out)[(size_t)b * NN + i * TT + t] = a;
}

extern "C" void kernel_launch(void* const* d_in, const int* in_sizes, int n_in,
                              void* d_out, int out_size) {
    const float* x = (const float*)d_in[0];
    const float* w = (const float*)d_in[1];
    float* out = (float*)d_out;
    (void)in_sizes; (void)n_in; (void)out_size;

    cudaFuncSetAttribute(fused_retina_kernel,
                         cudaFuncAttributeMaxDynamicSharedMemorySize, SMEM_BYTES);
    fused_retina_kernel<<<UNITS, NTHREADS, SMEM_BYTES>>>(x, w);
    reduce_scatter_kernel<<<(TB * CC * 4) / 256, 256>>>(out);
}

// round 12
// speedup vs baseline: 1.6343x; 1.0997x over previous
#include <cuda_runtime.h>
#include <stdint.h>

// B=8, T=8, C=1024, F=4, N=8192
#define TT 8
#define BB 8
#define CC 1024
#define FF 4
#define NN (TT*CC)
#define TB 64                   // (t,b) pairs
#define SW 16                   // strip width (columns staged in smem)
#define JQ 16                   // column units per (t,b)
#define UNITS (TB*JQ)           // 1024 CTAs
#define STRIPS 4                // 64 cols per unit / SW
#define NTHREADS 512            // 2 CTAs/SM -> 1024 thr/SM, 64 regs/thread
#define KITER 32                // 1024 rows / 32 row-groups
#define NSTRIDE 1026            // EVEN stride: half-warps hit opposite bank parity
#define SMEM_BYTES ((SW*NSTRIDE + SW*FF + SW)*4)   // 65984 B -> 2 CTAs/SM

// per-unit partial results [unit][i][f] : 16 MB scratch
__device__ float g_partial[(size_t)UNITS * CC * FF];

__device__ __forceinline__ uint32_t tf_rotl(uint32_t x, int d) {
    return __funnelshift_l(x, x, d);
}

// JAX threefry2x32 partitionable: key=(0,42), counter=(0,e), out = x0^x1.
// Takes y = e + 42 (key pre-injected). Round 1 simplified (x0 starts 0);
// key-schedule x0-injections fused into the next round-add (IADD3).
__device__ __forceinline__ uint32_t threefry_bits(uint32_t y) {
    const uint32_t K1 = 42u;
    const uint32_t K2 = 0x1BD11BDAu ^ 42u;
    uint32_t x0 = y;
    uint32_t x1 = tf_rotl(y, 13) ^ y;
#define TF_R(d) { x0 += x1; x1 = tf_rotl(x1,(d)) ^ x0; }
    TF_R(15) TF_R(26) TF_R(6)
    x1 += K2 + 1u;
    x0 += x1 + K1;
    x1 = tf_rotl(x1, 17) ^ x0;
    TF_R(29) TF_R(16) TF_R(24)
    x1 += 2u;
    x0 += x1 + K2;
    x1 = tf_rotl(x1, 13) ^ x0;
    TF_R(15) TF_R(26) TF_R(6)
    x1 += K1 + 3u;
    x0 += x1;
    x1 = tf_rotl(x1, 17) ^ x0;
    TF_R(29) TF_R(16) TF_R(24)
    x1 += K2 + 4u;
    x0 += x1 + K1;
    x1 = tf_rotl(x1, 13) ^ x0;
    TF_R(15) TF_R(26) TF_R(6)
    return (x0 + K2) ^ (x1 + 5u);
#undef TF_R
}

__device__ __forceinline__ float ex2_fast(float a) {
    float r;
    asm("ex2.approx.ftz.f32 %0, %1;" : "=f"(r) : "f"(a));
    return r;
}
__device__ __forceinline__ unsigned long long pack2(float v) {
    unsigned long long d;
    const uint32_t r = __float_as_uint(v);
    asm("mov.b64 %0, {%1, %1};" : "=l"(d) : "r"(r));
    return d;
}
__device__ __forceinline__ void ffma2(unsigned long long& acc,
                                      unsigned long long a,
                                      unsigned long long b) {
    asm("fma.rn.f32x2 %0, %1, %2, %0;" : "+l"(acc) : "l"(a), "l"(b));
}

// One unit = (tb, jq): 64 columns x 1024 rows of one (t,b) weight matrix.
// Per strip: num = exp(w + g) up to the softmax-invariant scale, computed as
// ex2(w*log2e - log2(-ln u)). -ln u: exact v=1-u (Sterbenz) + 3-term series
// for u->1 (relative accuracy where it matters), MUFU lg2 elsewhere.
__global__ __launch_bounds__(NTHREADS, 2)
void fused_retina_kernel(const float* __restrict__ x,
                         const float* __restrict__ w) {
    const int unit = blockIdx.x;
    const int tb = unit >> 4;
    const int jq = unit & (JQ - 1);
    const int t  = tb >> 3;
    const int b  = tb & 7;
    const int jbase = jq * (STRIPS * SW);

    extern __shared__ float smem[];
    float* num  = smem;                     // [SW][NSTRIDE]
    float* sxs  = num + SW * NSTRIDE;       // [SW][FF], 16B aligned
    float* csum = sxs + SW * FF;            // [SW]

    const int tid = threadIdx.x;
    const int c   = tid & (SW - 1);         // column within strip
    const int r   = tid >> 4;               // 0..31 row group

    unsigned long long a0[2] = {0ull, 0ull};  // packed f32x2 accum, row tid
    unsigned long long a1[2] = {0ull, 0ull};  // row tid + 512
    const uint32_t ebase = ((uint32_t)tb << 20);

    for (int s = 0; s < STRIPS; ++s) {
        const int j0 = jbase + s * SW;
        if (tid < SW) csum[tid] = 0.f;
        __syncthreads();

        // ---- phase 1: hash + numerator + column partial sums ----
        const int j = j0 + c;
        const float* wcol = w + ((size_t)tb << 20) + ((size_t)r << 10) + j;
        // counter with key pre-injected: y = e + 42
        const uint32_t y0 = (ebase | ((uint32_t)r << 10) | (uint32_t)j) + 42u;
        float part = 0.f;
        #pragma unroll 8
        for (int k = 0; k < KITER; ++k) {
            const int i = (k << 5) + r;
            const float ww = __ldg(wcol + ((size_t)k << 15));
            const uint32_t bits = threefry_bits(y0 + ((uint32_t)k << 15));
            // (bits>>9)|0x3f800000 as IMAD.HI + IADD (exact, disjoint bits)
            const uint32_t ub = __umulhi(bits, 1u << 23) + 0x3f800000u;
            const float f = __uint_as_float(ub) - 1.0f;
            const float u = fmaxf(f, 1.17549435e-38f);
            // -ln u: exact series near u=1, else lg2(u) * -ln2
            const float v = 1.0f - u;
            const float poly = fmaf(v * v, fmaf(v, 0.33333333f, 0.5f), v);
            const float l2u = __log2f(u);
            const float p = (v <= 0.015625f) ? poly : (l2u * -0.69314718f);
            // nv = 2^(w*log2e - log2(p)) = exp(w)/(-ln u)
            const float nv = ex2_fast(fmaf(ww, 1.44269504f, -__log2f(p)));
            num[c * NSTRIDE + i] = nv;
            part += nv;
        }
        // lanes l and l^16 share a column: pre-reduce, then 16 atomics/warp
        part += __shfl_xor_sync(0xffffffffu, part, 16);
        if ((tid & 31) < SW) atomicAdd(&csum[c], part);
        __syncthreads();

        // ---- scaled gather: sxs[jj][f] = x[b, jg*8+t, f] / colsum[jj] ----
        if (tid < SW * FF) {
            const int cc2 = tid >> 2, ff = tid & 3;
            const int jg = j0 + cc2;
            const float gx = x[((size_t)b * NN + jg * TT + t) * FF + ff];
            sxs[tid] = gx / csum[cc2];
        }
        __syncthreads();

        // ---- phase 2: acc += num[row, jj] * sxs[jj][:] (f32x2 packed) ----
        #pragma unroll
        for (int jj = 0; jj < SW; ++jj) {
            const ulonglong2 s2 =
                *reinterpret_cast<const ulonglong2*>(&sxs[jj * FF]);
            const unsigned long long nv0 = pack2(num[jj * NSTRIDE + tid]);
            const unsigned long long nv1 =
                pack2(num[jj * NSTRIDE + tid + NTHREADS]);
            ffma2(a0[0], nv0, s2.x);
            ffma2(a0[1], nv0, s2.y);
            ffma2(a1[0], nv1, s2.x);
            ffma2(a1[1], nv1, s2.y);
        }
        __syncthreads();
    }

    ulonglong2* p = reinterpret_cast<ulonglong2*>(g_partial) +
                    ((size_t)unit * CC + tid);
    p[0]        = make_ulonglong2(a0[0], a0[1]);
    p[NTHREADS] = make_ulonglong2(a1[0], a1[1]);
}

// Reduce: 2 threads per output (8 partials each), shfl combine, scatter.
__global__ void reduce_scatter_kernel(float* __restrict__ out) {
    const int gid = blockIdx.x * blockDim.x + threadIdx.x;  // [0, TB*CC*2)
    const int o  = gid >> 1;
    const int h  = gid & 1;
    const int i  = o & (CC - 1);
    const int tb = o >> 10;
    const int t = tb >> 3, b = tb & 7;
    const float4* pp = reinterpret_cast<const float4*>(g_partial);
    float4 a = make_float4(0.f, 0.f, 0.f, 0.f);
    #pragma unroll
    for (int q = 0; q < 8; ++q) {
        const float4 p = pp[(size_t)(tb * JQ + h * 8 + q) * CC + i];
        a.x += p.x; a.y += p.y; a.z += p.z; a.w += p.w;
    }
    a.x += __shfl_xor_sync(0xffffffffu, a.x, 1);
    a.y += __shfl_xor_sync(0xffffffffu, a.y, 1);
    a.z += __shfl_xor_sync(0xffffffffu, a.z, 1);
    a.w += __shfl_xor_sync(0xffffffffu, a.w, 1);
    if (h == 0)
        reinterpret_cast<float4*>(out)[(size_t)b * NN + i * TT + t] = a;
}

extern "C" void kernel_launch(void* const* d_in, const int* in_sizes, int n_in,
                              void* d_out, int out_size) {
    const float* x = (const float*)d_in[0];
    const float* w = (const float*)d_in[1];
    float* out = (float*)d_out;
    (void)in_sizes; (void)n_in; (void)out_size;

    cudaFuncSetAttribute(fused_retina_kernel,
                         cudaFuncAttributeMaxDynamicSharedMemorySize, SMEM_BYTES);
    fused_retina_kernel<<<UNITS, NTHREADS, SMEM_BYTES>>>(x, w);
    reduce_scatter_kernel<<<(TB * CC * 2) / 256, 256>>>(out);
}